// round 9
// baseline (speedup 1.0000x reference)
#include <cuda_runtime.h>
#include <cstdint>

#define NB 8
#define NPTS 16384
#define NPOINT 512
#define NSAMPLE 32
#define CIN 64

// ---------------- scratch ----------------
__device__ int g_group_idx[NB * NPOINT * NSAMPLE];

// ---------------- packed f32x2 helpers ----------------
__device__ __forceinline__ unsigned long long pk2(float lo, float hi) {
    unsigned long long r;
    asm("mov.b64 %0, {%1, %2};" : "=l"(r) : "r"(__float_as_uint(lo)), "r"(__float_as_uint(hi)));
    return r;
}
__device__ __forceinline__ void upk2(float& lo, float& hi, unsigned long long v) {
    unsigned int a, b;
    asm("mov.b64 {%0, %1}, %2;" : "=r"(a), "=r"(b) : "l"(v));
    lo = __uint_as_float(a); hi = __uint_as_float(b);
}
__device__ __forceinline__ unsigned long long add2(unsigned long long a, unsigned long long b) {
    unsigned long long r; asm("add.rn.f32x2 %0, %1, %2;" : "=l"(r) : "l"(a), "l"(b)); return r;
}
__device__ __forceinline__ unsigned long long mul2(unsigned long long a, unsigned long long b) {
    unsigned long long r; asm("mul.rn.f32x2 %0, %1, %2;" : "=l"(r) : "l"(a), "l"(b)); return r;
}
__device__ __forceinline__ unsigned long long fma2(unsigned long long a, unsigned long long b,
                                                   unsigned long long c) {
    unsigned long long r;
    asm("fma.rn.f32x2 %0, %1, %2, %3;" : "=l"(r) : "l"(a), "l"(b), "l"(c));
    return r;
}
__device__ __forceinline__ uint32_t sm_addr(const void* p) {
    return (uint32_t)__cvta_generic_to_shared(p);
}
__device__ __forceinline__ unsigned redux_max_u32(unsigned v) {
    unsigned r; asm("redux.sync.max.u32 %0, %1, 0xffffffff;" : "=r"(r) : "r"(v)); return r;
}
__device__ __forceinline__ unsigned redux_min_u32(unsigned v) {
    unsigned r; asm("redux.sync.min.u32 %0, %1, 0xffffffff;" : "=r"(r) : "r"(v)); return r;
}

// =====================================================================
// Kernel 1: furthest point sampling (unchanged round-7 best).
// =====================================================================
extern __shared__ unsigned char dynsm[];

__global__ void __launch_bounds__(256, 1) __cluster_dims__(8, 1, 1)
fps_kernel(const float* __restrict__ xyz, float* __restrict__ out_xyz) {
    __shared__ alignas(16) float slots[2][8][8];
    __shared__ alignas(16) float sred[8][8];

    const int t = threadIdx.x;
    const int lane = t & 31;
    const int w = t >> 5;
    const int b = blockIdx.x >> 3;
    const int rank = blockIdx.x & 7;
    const float* base = xyz + (size_t)b * NPTS * 3;
    const int ctaBase = rank * 2048;

    unsigned long long cx[4], cy[4], cz[4];
    float dist[8];
    const float INF = __int_as_float(0x7f800000);
#pragma unroll
    for (int j = 0; j < 4; j++) {
        int p0 = ctaBase + t + (2 * j) * 256;
        int p1 = p0 + 256;
        float x0 = base[p0 * 3 + 0], y0 = base[p0 * 3 + 1], z0 = base[p0 * 3 + 2];
        float x1 = base[p1 * 3 + 0], y1 = base[p1 * 3 + 1], z1 = base[p1 * 3 + 2];
        cx[j] = pk2(x0, x1);
        cy[j] = pk2(y0, y1);
        cz[j] = pk2(z0, z1);
        dist[2 * j] = INF; dist[2 * j + 1] = INF;
    }

    float lx = __ldg(base + 0), ly = __ldg(base + 1), lz = __ldg(base + 2);

    asm volatile("barrier.cluster.arrive.aligned;" ::: "memory");
    asm volatile("barrier.cluster.wait.aligned;" ::: "memory");

    for (int it = 0; it < NPOINT; it++) {
        if (rank == 0 && t == 0) {
            out_xyz[(b * NPOINT + it) * 3 + 0] = lx;
            out_xyz[(b * NPOINT + it) * 3 + 1] = ly;
            out_xyz[(b * NPOINT + it) * 3 + 2] = lz;
        }
        if (it == NPOINT - 1) break;

        unsigned long long nqx = pk2(-lx, -lx);
        unsigned long long nqy = pk2(-ly, -ly);
        unsigned long long nqz = pk2(-lz, -lz);

        unsigned vb = 0u, vidx = 0u;
#pragma unroll
        for (int j = 0; j < 4; j++) {
            unsigned long long dx = add2(cx[j], nqx); dx = mul2(dx, dx);
            unsigned long long dy = add2(cy[j], nqy); dy = mul2(dy, dy);
            unsigned long long dz = add2(cz[j], nqz); dz = mul2(dz, dz);
            unsigned long long ss = add2(dx, dy);
            ss = add2(ss, dz);
            float d0, d1; upk2(d0, d1, ss);
            float n0 = fminf(dist[2 * j], d0);     dist[2 * j] = n0;
            float n1 = fminf(dist[2 * j + 1], d1); dist[2 * j + 1] = n1;
            unsigned b0 = __float_as_uint(n0);
            unsigned b1 = __float_as_uint(n1);
            if (b0 > vb) { vb = b0; vidx = (unsigned)(ctaBase + t + (2 * j) * 256); }
            if (b1 > vb) { vb = b1; vidx = (unsigned)(ctaBase + t + (2 * j + 1) * 256); }
        }

        unsigned wmax = redux_max_u32(vb);
        unsigned cand = (vb == wmax) ? vidx : 0xffffffffu;
        unsigned wimin = redux_min_u32(cand);

        {
            int off2 = (int)wimin - ctaBase;
            if ((off2 & 255) == t) {
                int j = off2 >> 8;
                int jj = j >> 1, ee = j & 1;
                float a0, a1, x, y, z;
                upk2(a0, a1, cx[jj]); x = ee ? a1 : a0;
                upk2(a0, a1, cy[jj]); y = ee ? a1 : a0;
                upk2(a0, a1, cz[jj]); z = ee ? a1 : a0;
                sred[w][0] = __uint_as_float(wmax);
                sred[w][1] = __uint_as_float(~wimin);
                sred[w][2] = x; sred[w][3] = y; sred[w][4] = z;
            }
        }
        __syncthreads();

        if (w == 0) {
            unsigned long long bk = 0ull;
            float bx = 0.0f, by = 0.0f, bz = 0.0f;
#pragma unroll
            for (int i = 0; i < 8; i++) {
                float4 s4 = *(const float4*)&sred[i][0];
                unsigned long long k = ((unsigned long long)__float_as_uint(s4.x) << 32)
                                       | (unsigned)__float_as_uint(s4.y);
                float z = sred[i][4];
                if (k > bk) { bk = k; bx = s4.z; by = s4.w; bz = z; }
            }
            if (lane < 8) {
                uint32_t la = sm_addr(&slots[it & 1][rank][0]);
                uint32_t ra;
                asm("mapa.shared::cluster.u32 %0, %1, %2;" : "=r"(ra) : "r"(la), "r"(lane));
                asm volatile("st.shared::cluster.v4.f32 [%0], {%1, %2, %3, %4};"
                             :: "r"(ra),
                                "f"(__uint_as_float((unsigned)(bk >> 32))),
                                "f"(__uint_as_float((unsigned)bk)),
                                "f"(bx), "f"(by) : "memory");
                asm volatile("st.shared::cluster.f32 [%0], %1;"
                             :: "r"(ra + 16), "f"(bz) : "memory");
            }
        }

        asm volatile("barrier.cluster.arrive.aligned;" ::: "memory");
        asm volatile("barrier.cluster.wait.aligned;" ::: "memory");

        {
            unsigned long long bk = 0ull;
            float bx = 0.0f, by = 0.0f, bz = 0.0f;
#pragma unroll
            for (int i = 0; i < 8; i++) {
                const float* sp = &slots[it & 1][i][0];
                float4 s4 = *(const float4*)sp;
                unsigned long long k = ((unsigned long long)__float_as_uint(s4.x) << 32)
                                       | (unsigned)__float_as_uint(s4.y);
                float z = sp[4];
                if (k > bk) { bk = k; bx = s4.z; by = s4.w; bz = z; }
            }
            lx = bx; ly = by; lz = bz;
        }
    }

    asm volatile("barrier.cluster.arrive.aligned;" ::: "memory");
    asm volatile("barrier.cluster.wait.aligned;" ::: "memory");
}

// =====================================================================
// Kernel 2: ball query (unchanged round-7 best).
// =====================================================================
__global__ void __launch_bounds__(256) ballquery_kernel(const float* __restrict__ xyz,
                                                        const float* __restrict__ newxyz) {
    int w = (blockIdx.x * blockDim.x + threadIdx.x) >> 5;
    int lane = threadIdx.x & 31;
    if (w >= NB * NPOINT) return;
    int b = w >> 9;
    const float* base = xyz + (size_t)b * NPTS * 3;

    float qx = newxyz[w * 3 + 0];
    float qy = newxyz[w * 3 + 1];
    float qz = newxyz[w * 3 + 2];
    const float r2 = 0.04f;

    int cnt = 0, first = -1;
    int* gout = g_group_idx + w * 32;
    for (int bs = 0; bs < NPTS && cnt < 32; bs += 32) {
        int p = bs + lane;
        float x = base[p * 3 + 0], y = base[p * 3 + 1], z = base[p * 3 + 2];
        float dx = __fsub_rn(qx, x);
        float dy = __fsub_rn(qy, y);
        float dz = __fsub_rn(qz, z);
        float d2 = __fadd_rn(__fadd_rn(__fmul_rn(dx, dx), __fmul_rn(dy, dy)), __fmul_rn(dz, dz));
        bool pred = (d2 <= r2);
        unsigned m = __ballot_sync(0xffffffffu, pred);
        if (m) {
            if (first < 0) first = bs + (__ffs(m) - 1);
            int pre = __popc(m & ((1u << lane) - 1u));
            if (pred && (cnt + pre) < 32) gout[cnt + pre] = p;
            cnt += __popc(m);
            if (cnt > 32) cnt = 32;
        }
    }
    for (int j = cnt + lane; j < 32; j += 32) gout[j] = first;
}

// =====================================================================
// Kernel 3: fused gather + MLP + maxpool, FFMA2, 256 threads / 1 CTA per
// SM, TWO groups per iteration (tid bit 7 = half). Weights staged once
// and shared by both halves; per-group XT2/HT2/PM duplicated.
// SMEM ~149KB (fits 1 CTA; no occupancy cliff: throughput comes from
// 2 groups in flight, same 2 warps/SMSP as the round-7 scalar config).
// =====================================================================
// float-unit offsets
#define SM_W0   0        // [67][64]
#define SM_W1   4288     // [64][64]
#define SM_W2   8384     // [64][128]
#define SM_SC0  16576
#define SM_SH0  16640
#define SM_SC1  16704
#define SM_SH1  16768
#define SM_SC2  16832
#define SM_SH2  16960    // ..17088
#define SM_GRP  17088    // per-group block base
// per-group block (floats): XT2 u64[67][36]=4824, HT2 u64[64][36]=4608,
// PM 1024, GIX 32, CTR 3, pad 1  => 10492
#define GRP_XT2 0
#define GRP_HT2 4824
#define GRP_PM  9432
#define GRP_GIX 10456
#define GRP_CTR 10488
#define GRP_FLOATS 10492
#define SM_FLOATS (SM_GRP + 2 * GRP_FLOATS)
#define SM_BYTES (SM_FLOATS * 4)

__global__ void __launch_bounds__(256, 1) mlp_kernel(
    const float* __restrict__ xyz, const float* __restrict__ feat,
    const float* __restrict__ newxyz,
    const float* __restrict__ w0, const float* __restrict__ g0, const float* __restrict__ b0,
    const float* __restrict__ m0, const float* __restrict__ v0,
    const float* __restrict__ w1, const float* __restrict__ g1, const float* __restrict__ b1,
    const float* __restrict__ m1, const float* __restrict__ v1,
    const float* __restrict__ w2, const float* __restrict__ g2, const float* __restrict__ b2,
    const float* __restrict__ m2, const float* __restrict__ v2,
    float* __restrict__ outf) {
    float* sm = (float*)dynsm;
    float* W0  = sm + SM_W0;
    float* W1  = sm + SM_W1;
    float* W2  = sm + SM_W2;
    float* SC0 = sm + SM_SC0; float* SH0 = sm + SM_SH0;
    float* SC1 = sm + SM_SC1; float* SH1 = sm + SM_SH1;
    float* SC2 = sm + SM_SC2; float* SH2 = sm + SM_SH2;

    const int tid = threadIdx.x;
    const int half = tid >> 7;          // 0/1: which group this thread serves
    const int wg_tid = tid & 127;

    float* grp = sm + SM_GRP + half * GRP_FLOATS;
    unsigned long long* XT2 = (unsigned long long*)(grp + GRP_XT2);
    unsigned long long* HT2 = (unsigned long long*)(grp + GRP_HT2);
    float* PM  = grp + GRP_PM;
    int*   GIX = (int*)(grp + GRP_GIX);
    float* CTR = grp + GRP_CTR;

    // stage weights transposed: W[c][o] (all 256 threads)
    for (int e = tid; e < 64 * 67; e += 256) { int o = e / 67, c = e - o * 67; W0[c * 64 + o] = w0[e]; }
    for (int e = tid; e < 64 * 64; e += 256) { int o = e >> 6, c = e & 63; W1[c * 64 + o] = w1[e]; }
    for (int e = tid; e < 128 * 64; e += 256) { int o = e >> 6, c = e & 63; W2[c * 128 + o] = w2[e]; }
    if (tid < 64) {
        float s0 = g0[tid] * rsqrtf(v0[tid] + 1e-5f); SC0[tid] = s0; SH0[tid] = b0[tid] - m0[tid] * s0;
        float s1 = g1[tid] * rsqrtf(v1[tid] + 1e-5f); SC1[tid] = s1; SH1[tid] = b1[tid] - m1[tid] * s1;
    }
    if (tid < 128) {
        float s2 = g2[tid] * rsqrtf(v2[tid] + 1e-5f); SC2[tid] = s2; SH2[tid] = b2[tid] - m2[tid] * s2;
    }
    __syncthreads();

    const int ko = wg_tid & 7;    // row tile base = 4*ko
    const int oo = wg_tid >> 3;   // 0..15

    // 2048 group-pairs; CTA p handles pairs p, p+148, ...
    for (int p = blockIdx.x; p < (NB * NPOINT) / 2; p += gridDim.x) {
        int g = 2 * p + half;
        int b = g >> 9, s = g & 511;

        if (wg_tid < 32) GIX[wg_tid] = g_group_idx[g * 32 + wg_tid];
        if (wg_tid < 3)  CTR[wg_tid] = newxyz[g * 3 + wg_tid];
        __syncthreads();

        // gather features -> XT2 rows 3..66 as (v,v) pairs
#pragma unroll
        for (int i = 0; i < 4; i++) {
            int fi = wg_tid + i * 128;
            int k = fi >> 4, c4 = fi & 15;
            float4 fv = *((const float4*)(feat + ((size_t)b * NPTS + GIX[k]) * CIN) + c4);
            int r = 3 + 4 * c4;
            XT2[(r + 0) * 36 + k] = pk2(fv.x, fv.x);
            XT2[(r + 1) * 36 + k] = pk2(fv.y, fv.y);
            XT2[(r + 2) * 36 + k] = pk2(fv.z, fv.z);
            XT2[(r + 3) * 36 + k] = pk2(fv.w, fv.w);
        }
        if (wg_tid < 32) {
            const float* pp = xyz + ((size_t)b * NPTS + GIX[wg_tid]) * 3;
            float d0 = pp[0] - CTR[0], d1 = pp[1] - CTR[1], d2 = pp[2] - CTR[2];
            XT2[0 * 36 + wg_tid] = pk2(d0, d0);
            XT2[1 * 36 + wg_tid] = pk2(d1, d1);
            XT2[2 * 36 + wg_tid] = pk2(d2, d2);
        }
        __syncthreads();

        // ---- layer 0: rows 4ko..+3, cols 4oo..+3 (2 col-pairs) ----
        unsigned long long accp[4][2];
#pragma unroll
        for (int i = 0; i < 4; i++) { accp[i][0] = 0ull; accp[i][1] = 0ull; }
        for (int c = 0; c < 67; c++) {
            const unsigned long long* xp = XT2 + c * 36 + 4 * ko;
            ulonglong2 xa = *(const ulonglong2*)xp;
            ulonglong2 xb = *(const ulonglong2*)(xp + 2);
            ulonglong2 wp = *(const ulonglong2*)(W0 + c * 64 + 4 * oo);
            accp[0][0] = fma2(xa.x, wp.x, accp[0][0]);
            accp[0][1] = fma2(xa.x, wp.y, accp[0][1]);
            accp[1][0] = fma2(xa.y, wp.x, accp[1][0]);
            accp[1][1] = fma2(xa.y, wp.y, accp[1][1]);
            accp[2][0] = fma2(xb.x, wp.x, accp[2][0]);
            accp[2][1] = fma2(xb.x, wp.y, accp[2][1]);
            accp[3][0] = fma2(xb.y, wp.x, accp[3][0]);
            accp[3][1] = fma2(xb.y, wp.y, accp[3][1]);
        }
#pragma unroll
        for (int jp = 0; jp < 2; jp++) {
            int o0 = 4 * oo + 2 * jp, o1 = o0 + 1;
            float sc0 = SC0[o0], sh0 = SH0[o0], sc1 = SC0[o1], sh1 = SH0[o1];
#pragma unroll
            for (int r = 0; r < 4; r++) {
                float a0, a1; upk2(a0, a1, accp[r][jp]);
                float h0 = fmaxf(fmaf(a0, sc0, sh0), 0.0f);
                float h1 = fmaxf(fmaf(a1, sc1, sh1), 0.0f);
                HT2[o0 * 36 + 4 * ko + r] = pk2(h0, h0);
                HT2[o1 * 36 + 4 * ko + r] = pk2(h1, h1);
            }
        }
        __syncthreads();

        // ---- layer 1 ----
#pragma unroll
        for (int i = 0; i < 4; i++) { accp[i][0] = 0ull; accp[i][1] = 0ull; }
        for (int c = 0; c < 64; c++) {
            const unsigned long long* xp = HT2 + c * 36 + 4 * ko;
            ulonglong2 xa = *(const ulonglong2*)xp;
            ulonglong2 xb = *(const ulonglong2*)(xp + 2);
            ulonglong2 wp = *(const ulonglong2*)(W1 + c * 64 + 4 * oo);
            accp[0][0] = fma2(xa.x, wp.x, accp[0][0]);
            accp[0][1] = fma2(xa.x, wp.y, accp[0][1]);
            accp[1][0] = fma2(xa.y, wp.x, accp[1][0]);
            accp[1][1] = fma2(xa.y, wp.y, accp[1][1]);
            accp[2][0] = fma2(xb.x, wp.x, accp[2][0]);
            accp[2][1] = fma2(xb.x, wp.y, accp[2][1]);
            accp[3][0] = fma2(xb.y, wp.x, accp[3][0]);
            accp[3][1] = fma2(xb.y, wp.y, accp[3][1]);
        }
        __syncthreads();   // all reads of HT2 done before overwrite
#pragma unroll
        for (int jp = 0; jp < 2; jp++) {
            int o0 = 4 * oo + 2 * jp, o1 = o0 + 1;
            float sc0 = SC1[o0], sh0 = SH1[o0], sc1 = SC1[o1], sh1 = SH1[o1];
#pragma unroll
            for (int r = 0; r < 4; r++) {
                float a0, a1; upk2(a0, a1, accp[r][jp]);
                float h0 = fmaxf(fmaf(a0, sc0, sh0), 0.0f);
                float h1 = fmaxf(fmaf(a1, sc1, sh1), 0.0f);
                HT2[o0 * 36 + 4 * ko + r] = pk2(h0, h0);
                HT2[o1 * 36 + 4 * ko + r] = pk2(h1, h1);
            }
        }
        __syncthreads();

        // ---- layer 2: cols 8oo..+7 (4 col-pairs) + ReLU + partial max ----
        unsigned long long acc2p[4][4];
#pragma unroll
        for (int i = 0; i < 4; i++)
#pragma unroll
            for (int j = 0; j < 4; j++) acc2p[i][j] = 0ull;
        for (int c = 0; c < 64; c++) {
            const unsigned long long* xp = HT2 + c * 36 + 4 * ko;
            ulonglong2 xa = *(const ulonglong2*)xp;
            ulonglong2 xb = *(const ulonglong2*)(xp + 2);
            ulonglong2 wpa = *(const ulonglong2*)(W2 + c * 128 + 8 * oo);
            ulonglong2 wpb = *(const ulonglong2*)(W2 + c * 128 + 8 * oo + 4);
            acc2p[0][0] = fma2(xa.x, wpa.x, acc2p[0][0]);
            acc2p[0][1] = fma2(xa.x, wpa.y, acc2p[0][1]);
            acc2p[0][2] = fma2(xa.x, wpb.x, acc2p[0][2]);
            acc2p[0][3] = fma2(xa.x, wpb.y, acc2p[0][3]);
            acc2p[1][0] = fma2(xa.y, wpa.x, acc2p[1][0]);
            acc2p[1][1] = fma2(xa.y, wpa.y, acc2p[1][1]);
            acc2p[1][2] = fma2(xa.y, wpb.x, acc2p[1][2]);
            acc2p[1][3] = fma2(xa.y, wpb.y, acc2p[1][3]);
            acc2p[2][0] = fma2(xb.x, wpa.x, acc2p[2][0]);
            acc2p[2][1] = fma2(xb.x, wpa.y, acc2p[2][1]);
            acc2p[2][2] = fma2(xb.x, wpb.x, acc2p[2][2]);
            acc2p[2][3] = fma2(xb.x, wpb.y, acc2p[2][3]);
            acc2p[3][0] = fma2(xb.y, wpa.x, acc2p[3][0]);
            acc2p[3][1] = fma2(xb.y, wpa.y, acc2p[3][1]);
            acc2p[3][2] = fma2(xb.y, wpb.x, acc2p[3][2]);
            acc2p[3][3] = fma2(xb.y, wpb.y, acc2p[3][3]);
        }
#pragma unroll
        for (int jp = 0; jp < 4; jp++) {
            int o0 = 8 * oo + 2 * jp, o1 = o0 + 1;
            float sc0 = SC2[o0], sh0 = SH2[o0], sc1 = SC2[o1], sh1 = SH2[o1];
            float mv0 = 0.0f, mv1 = 0.0f;
#pragma unroll
            for (int r = 0; r < 4; r++) {
                float a0, a1; upk2(a0, a1, acc2p[r][jp]);
                mv0 = fmaxf(mv0, fmaf(a0, sc0, sh0));
                mv1 = fmaxf(mv1, fmaf(a1, sc1, sh1));
            }
            PM[oo * 64 + (2 * jp) * 8 + ko] = mv0;
            PM[oo * 64 + (2 * jp + 1) * 8 + ko] = mv1;
        }
        __syncthreads();

        // final reduce over the 8 row-tiles and write (B,128,S)
        {
            int o = wg_tid;
            const float* pp = PM + (o >> 3) * 64 + (o & 7) * 8;
            float mv = pp[0];
#pragma unroll
            for (int kk = 1; kk < 8; kk++) mv = fmaxf(mv, pp[kk]);
            outf[((size_t)b * 128 + o) * NPOINT + s] = mv;
        }
        __syncthreads();
    }
}

// =====================================================================
// launcher (sequential)
// =====================================================================
extern "C" void kernel_launch(void* const* d_in, const int* in_sizes, int n_in,
                              void* d_out, int out_size) {
    const float* xyz  = (const float*)d_in[0];
    const float* feat = (const float*)d_in[1];
    const float* w0 = (const float*)d_in[2];
    const float* g0 = (const float*)d_in[3];
    const float* b0 = (const float*)d_in[4];
    const float* m0 = (const float*)d_in[5];
    const float* v0 = (const float*)d_in[6];
    const float* w1 = (const float*)d_in[7];
    const float* g1 = (const float*)d_in[8];
    const float* b1 = (const float*)d_in[9];
    const float* m1 = (const float*)d_in[10];
    const float* v1 = (const float*)d_in[11];
    const float* w2 = (const float*)d_in[12];
    const float* g2 = (const float*)d_in[13];
    const float* b2 = (const float*)d_in[14];
    const float* m2 = (const float*)d_in[15];
    const float* v2 = (const float*)d_in[16];

    float* out = (float*)d_out;
    float* newxyz  = out;                          // (8,512,3)
    float* newfeat = out + NB * NPOINT * 3;        // (8,128,512)

    cudaFuncSetAttribute(mlp_kernel, cudaFuncAttributeMaxDynamicSharedMemorySize, SM_BYTES);

    fps_kernel<<<NB * 8, 256>>>(xyz, newxyz);
    ballquery_kernel<<<(NB * NPOINT * 32 + 255) / 256, 256>>>(xyz, newxyz);
    mlp_kernel<<<148, 256, SM_BYTES>>>(xyz, feat, newxyz,
                                       w0, g0, b0, m0, v0,
                                       w1, g1, b1, m1, v1,
                                       w2, g2, b2, m2, v2,
                                       newfeat);
}

// round 11
// speedup vs baseline: 1.2454x; 1.2454x over previous
#include <cuda_runtime.h>
#include <cstdint>

#define NB 8
#define NPTS 16384
#define NPOINT 512
#define NSAMPLE 32
#define CIN 64

// ---------------- scratch ----------------
__device__ int g_group_idx[NB * NPOINT * NSAMPLE];

// ---------------- packed f32x2 helpers ----------------
__device__ __forceinline__ unsigned long long pk2(float lo, float hi) {
    unsigned long long r;
    asm("mov.b64 %0, {%1, %2};" : "=l"(r) : "r"(__float_as_uint(lo)), "r"(__float_as_uint(hi)));
    return r;
}
__device__ __forceinline__ void upk2(float& lo, float& hi, unsigned long long v) {
    unsigned int a, b;
    asm("mov.b64 {%0, %1}, %2;" : "=r"(a), "=r"(b) : "l"(v));
    lo = __uint_as_float(a); hi = __uint_as_float(b);
}
__device__ __forceinline__ unsigned long long add2(unsigned long long a, unsigned long long b) {
    unsigned long long r; asm("add.rn.f32x2 %0, %1, %2;" : "=l"(r) : "l"(a), "l"(b)); return r;
}
__device__ __forceinline__ unsigned long long mul2(unsigned long long a, unsigned long long b) {
    unsigned long long r; asm("mul.rn.f32x2 %0, %1, %2;" : "=l"(r) : "l"(a), "l"(b)); return r;
}
__device__ __forceinline__ uint32_t sm_addr(const void* p) {
    return (uint32_t)__cvta_generic_to_shared(p);
}
__device__ __forceinline__ unsigned redux_max_u32(unsigned v) {
    unsigned r; asm("redux.sync.max.u32 %0, %1, 0xffffffff;" : "=r"(r) : "r"(v)); return r;
}
__device__ __forceinline__ unsigned redux_min_u32(unsigned v) {
    unsigned r; asm("redux.sync.min.u32 %0, %1, 0xffffffff;" : "=r"(r) : "r"(v)); return r;
}

// =====================================================================
// Kernel 1: furthest point sampling (round-7 best, unchanged).
// =====================================================================
extern __shared__ unsigned char dynsm[];

__global__ void __launch_bounds__(256, 1) __cluster_dims__(8, 1, 1)
fps_kernel(const float* __restrict__ xyz, float* __restrict__ out_xyz) {
    __shared__ alignas(16) float slots[2][8][8];
    __shared__ alignas(16) float sred[8][8];

    const int t = threadIdx.x;
    const int lane = t & 31;
    const int w = t >> 5;
    const int b = blockIdx.x >> 3;
    const int rank = blockIdx.x & 7;
    const float* base = xyz + (size_t)b * NPTS * 3;
    const int ctaBase = rank * 2048;

    unsigned long long cx[4], cy[4], cz[4];
    float dist[8];
    const float INF = __int_as_float(0x7f800000);
#pragma unroll
    for (int j = 0; j < 4; j++) {
        int p0 = ctaBase + t + (2 * j) * 256;
        int p1 = p0 + 256;
        float x0 = base[p0 * 3 + 0], y0 = base[p0 * 3 + 1], z0 = base[p0 * 3 + 2];
        float x1 = base[p1 * 3 + 0], y1 = base[p1 * 3 + 1], z1 = base[p1 * 3 + 2];
        cx[j] = pk2(x0, x1);
        cy[j] = pk2(y0, y1);
        cz[j] = pk2(z0, z1);
        dist[2 * j] = INF; dist[2 * j + 1] = INF;
    }

    float lx = __ldg(base + 0), ly = __ldg(base + 1), lz = __ldg(base + 2);

    asm volatile("barrier.cluster.arrive.aligned;" ::: "memory");
    asm volatile("barrier.cluster.wait.aligned;" ::: "memory");

    for (int it = 0; it < NPOINT; it++) {
        if (rank == 0 && t == 0) {
            out_xyz[(b * NPOINT + it) * 3 + 0] = lx;
            out_xyz[(b * NPOINT + it) * 3 + 1] = ly;
            out_xyz[(b * NPOINT + it) * 3 + 2] = lz;
        }
        if (it == NPOINT - 1) break;

        unsigned long long nqx = pk2(-lx, -lx);
        unsigned long long nqy = pk2(-ly, -ly);
        unsigned long long nqz = pk2(-lz, -lz);

        unsigned vb = 0u, vidx = 0u;
#pragma unroll
        for (int j = 0; j < 4; j++) {
            unsigned long long dx = add2(cx[j], nqx); dx = mul2(dx, dx);
            unsigned long long dy = add2(cy[j], nqy); dy = mul2(dy, dy);
            unsigned long long dz = add2(cz[j], nqz); dz = mul2(dz, dz);
            unsigned long long ss = add2(dx, dy);
            ss = add2(ss, dz);
            float d0, d1; upk2(d0, d1, ss);
            float n0 = fminf(dist[2 * j], d0);     dist[2 * j] = n0;
            float n1 = fminf(dist[2 * j + 1], d1); dist[2 * j + 1] = n1;
            unsigned b0 = __float_as_uint(n0);
            unsigned b1 = __float_as_uint(n1);
            if (b0 > vb) { vb = b0; vidx = (unsigned)(ctaBase + t + (2 * j) * 256); }
            if (b1 > vb) { vb = b1; vidx = (unsigned)(ctaBase + t + (2 * j + 1) * 256); }
        }

        unsigned wmax = redux_max_u32(vb);
        unsigned cand = (vb == wmax) ? vidx : 0xffffffffu;
        unsigned wimin = redux_min_u32(cand);

        {
            int off2 = (int)wimin - ctaBase;
            if ((off2 & 255) == t) {
                int j = off2 >> 8;
                int jj = j >> 1, ee = j & 1;
                float a0, a1, x, y, z;
                upk2(a0, a1, cx[jj]); x = ee ? a1 : a0;
                upk2(a0, a1, cy[jj]); y = ee ? a1 : a0;
                upk2(a0, a1, cz[jj]); z = ee ? a1 : a0;
                sred[w][0] = __uint_as_float(wmax);
                sred[w][1] = __uint_as_float(~wimin);
                sred[w][2] = x; sred[w][3] = y; sred[w][4] = z;
            }
        }
        __syncthreads();

        if (w == 0) {
            unsigned long long bk = 0ull;
            float bx = 0.0f, by = 0.0f, bz = 0.0f;
#pragma unroll
            for (int i = 0; i < 8; i++) {
                float4 s4 = *(const float4*)&sred[i][0];
                unsigned long long k = ((unsigned long long)__float_as_uint(s4.x) << 32)
                                       | (unsigned)__float_as_uint(s4.y);
                float z = sred[i][4];
                if (k > bk) { bk = k; bx = s4.z; by = s4.w; bz = z; }
            }
            if (lane < 8) {
                uint32_t la = sm_addr(&slots[it & 1][rank][0]);
                uint32_t ra;
                asm("mapa.shared::cluster.u32 %0, %1, %2;" : "=r"(ra) : "r"(la), "r"(lane));
                asm volatile("st.shared::cluster.v4.f32 [%0], {%1, %2, %3, %4};"
                             :: "r"(ra),
                                "f"(__uint_as_float((unsigned)(bk >> 32))),
                                "f"(__uint_as_float((unsigned)bk)),
                                "f"(bx), "f"(by) : "memory");
                asm volatile("st.shared::cluster.f32 [%0], %1;"
                             :: "r"(ra + 16), "f"(bz) : "memory");
            }
        }

        asm volatile("barrier.cluster.arrive.aligned;" ::: "memory");
        asm volatile("barrier.cluster.wait.aligned;" ::: "memory");

        {
            unsigned long long bk = 0ull;
            float bx = 0.0f, by = 0.0f, bz = 0.0f;
#pragma unroll
            for (int i = 0; i < 8; i++) {
                const float* sp = &slots[it & 1][i][0];
                float4 s4 = *(const float4*)sp;
                unsigned long long k = ((unsigned long long)__float_as_uint(s4.x) << 32)
                                       | (unsigned)__float_as_uint(s4.y);
                float z = sp[4];
                if (k > bk) { bk = k; bx = s4.z; by = s4.w; bz = z; }
            }
            lx = bx; ly = by; lz = bz;
        }
    }

    asm volatile("barrier.cluster.arrive.aligned;" ::: "memory");
    asm volatile("barrier.cluster.wait.aligned;" ::: "memory");
}

// =====================================================================
// Kernel 2: ball query with block-cooperative SMEM staging.
// One CTA (256 thr) = 8 query points of ONE batch. 16 chunks of 1024
// points staged coalesced (float4) into smem; each unfinished warp scans
// the chunk from LDS with the exact ordered ballot/prefix/append logic
// (first 32 in-radius ascending == reference sorted-take). Block stops
// when all 8 warps are done. Math identical to round-7 BQ (bit-exact).
// =====================================================================
__global__ void __launch_bounds__(256) ballquery_kernel(const float* __restrict__ xyz,
                                                        const float* __restrict__ newxyz) {
    __shared__ alignas(16) float pts[3072];   // 1024 points * 3 floats
    __shared__ int done_count;

    const int w = threadIdx.x >> 5;
    const int lane = threadIdx.x & 31;
    const int g = blockIdx.x * 8 + w;         // 0..4095, block = 8 pts of same batch
    const int b = g >> 9;
    const float* base = xyz + (size_t)b * NPTS * 3;
    const float r2 = 0.04f;   // f32(0.2*0.2 in double) — matches JAX scalar cast

    float qx = newxyz[g * 3 + 0];
    float qy = newxyz[g * 3 + 1];
    float qz = newxyz[g * 3 + 2];

    if (threadIdx.x == 0) done_count = 0;
    __syncthreads();

    int cnt = 0, first = -1;
    bool done = false;
    int* gout = g_group_idx + g * 32;

    for (int chunk = 0; chunk < 16; chunk++) {
        // coalesced stage: 3072 floats = 768 float4
        {
            const float4* src = (const float4*)(base + chunk * 3072);
            float4* dst = (float4*)pts;
#pragma unroll
            for (int i = 0; i < 3; i++) dst[threadIdx.x + i * 256] = src[threadIdx.x + i * 256];
        }
        __syncthreads();

        if (!done) {
            for (int q = 0; q < 32 && cnt < 32; q++) {
                int p_loc = q * 32 + lane;
                float x = pts[p_loc * 3 + 0];
                float y = pts[p_loc * 3 + 1];
                float z = pts[p_loc * 3 + 2];
                float dx = __fsub_rn(qx, x);
                float dy = __fsub_rn(qy, y);
                float dz = __fsub_rn(qz, z);
                float d2 = __fadd_rn(__fadd_rn(__fmul_rn(dx, dx), __fmul_rn(dy, dy)),
                                     __fmul_rn(dz, dz));
                bool pred = (d2 <= r2);
                unsigned m = __ballot_sync(0xffffffffu, pred);
                if (m) {
                    int p = chunk * 1024 + p_loc;
                    if (first < 0) first = chunk * 1024 + q * 32 + (__ffs(m) - 1);
                    int pre = __popc(m & ((1u << lane) - 1u));
                    if (pred && (cnt + pre) < 32) gout[cnt + pre] = p;
                    cnt += __popc(m);
                    if (cnt > 32) cnt = 32;
                }
            }
            if (cnt >= 32) {
                done = true;
                if (lane == 0) atomicAdd(&done_count, 1);
            }
        }
        __syncthreads();           // pts reads done + done_count settled
        if (done_count == 8) break;
    }

    // pad (query point itself is always in-radius, so first >= 0)
    for (int j = cnt + lane; j < 32; j += 32) gout[j] = first;
}

// =====================================================================
// Kernel 3: fused gather + MLP (round-7 scalar body, unchanged).
// =====================================================================
#define SM_W0   0        // [67][64]
#define SM_W1   4288     // [64][64]
#define SM_W2   8384     // [64][128]
#define SM_SC0  16576
#define SM_SH0  16640
#define SM_SC1  16704
#define SM_SH1  16768
#define SM_SC2  16832
#define SM_SH2  16960
#define SM_XT   17088    // [67][36]
#define SM_HT   19500    // [64][36]
#define SM_PM   21804    // [16][8][8]
#define SM_GIX  22828    // 32 ints
#define SM_CTR  22860    // 3 floats
#define SM_FLOATS 22864
#define SM_BYTES (SM_FLOATS * 4)

__global__ void __launch_bounds__(128, 2) mlp_kernel(
    const float* __restrict__ xyz, const float* __restrict__ feat,
    const float* __restrict__ newxyz,
    const float* __restrict__ w0, const float* __restrict__ g0, const float* __restrict__ b0,
    const float* __restrict__ m0, const float* __restrict__ v0,
    const float* __restrict__ w1, const float* __restrict__ g1, const float* __restrict__ b1,
    const float* __restrict__ m1, const float* __restrict__ v1,
    const float* __restrict__ w2, const float* __restrict__ g2, const float* __restrict__ b2,
    const float* __restrict__ m2, const float* __restrict__ v2,
    float* __restrict__ outf) {
    float* sm = (float*)dynsm;
    float* W0  = sm + SM_W0;
    float* W1  = sm + SM_W1;
    float* W2  = sm + SM_W2;
    float* SC0 = sm + SM_SC0; float* SH0 = sm + SM_SH0;
    float* SC1 = sm + SM_SC1; float* SH1 = sm + SM_SH1;
    float* SC2 = sm + SM_SC2; float* SH2 = sm + SM_SH2;
    float* XT  = sm + SM_XT;
    float* HT  = sm + SM_HT;
    float* PM  = sm + SM_PM;
    int*   GIX = (int*)(sm + SM_GIX);
    float* CTR = sm + SM_CTR;

    const int tid = threadIdx.x;

    for (int e = tid; e < 64 * 67; e += 128) { int o = e / 67, c = e - o * 67; W0[c * 64 + o] = w0[e]; }
    for (int e = tid; e < 64 * 64; e += 128) { int o = e >> 6, c = e & 63; W1[c * 64 + o] = w1[e]; }
    for (int e = tid; e < 128 * 64; e += 128) { int o = e >> 6, c = e & 63; W2[c * 128 + o] = w2[e]; }
    if (tid < 64) {
        float s0 = g0[tid] * rsqrtf(v0[tid] + 1e-5f); SC0[tid] = s0; SH0[tid] = b0[tid] - m0[tid] * s0;
        float s1 = g1[tid] * rsqrtf(v1[tid] + 1e-5f); SC1[tid] = s1; SH1[tid] = b1[tid] - m1[tid] * s1;
    }
    if (tid < 128) {
        float s2 = g2[tid] * rsqrtf(v2[tid] + 1e-5f); SC2[tid] = s2; SH2[tid] = b2[tid] - m2[tid] * s2;
    }
    __syncthreads();

    const int ko = tid & 7;
    const int oo = tid >> 3;

    for (int g = blockIdx.x; g < NB * NPOINT; g += gridDim.x) {
        int b = g >> 9, s = g & 511;
        if (tid < 32) GIX[tid] = g_group_idx[g * 32 + tid];
        if (tid < 3)  CTR[tid] = newxyz[g * 3 + tid];
        __syncthreads();

#pragma unroll
        for (int i = 0; i < 4; i++) {
            int fi = tid + i * 128;
            int k = fi >> 4, c4 = fi & 15;
            float4 fv = *((const float4*)(feat + ((size_t)b * NPTS + GIX[k]) * CIN) + c4);
            int r = 3 + 4 * c4;
            XT[(r + 0) * 36 + k] = fv.x;
            XT[(r + 1) * 36 + k] = fv.y;
            XT[(r + 2) * 36 + k] = fv.z;
            XT[(r + 3) * 36 + k] = fv.w;
        }
        if (tid < 32) {
            const float* p = xyz + ((size_t)b * NPTS + GIX[tid]) * 3;
            XT[0 * 36 + tid] = p[0] - CTR[0];
            XT[1 * 36 + tid] = p[1] - CTR[1];
            XT[2 * 36 + tid] = p[2] - CTR[2];
        }
        __syncthreads();

        float acc[4][4];
#pragma unroll
        for (int i = 0; i < 4; i++)
#pragma unroll
            for (int j = 0; j < 4; j++) acc[i][j] = 0.0f;
        for (int c = 0; c < 67; c++) {
            float4 xv = *(const float4*)(XT + c * 36 + 4 * ko);
            float4 wv = *(const float4*)(W0 + c * 64 + 4 * oo);
            float xs[4] = {xv.x, xv.y, xv.z, xv.w};
            float ws[4] = {wv.x, wv.y, wv.z, wv.w};
#pragma unroll
            for (int i = 0; i < 4; i++)
#pragma unroll
                for (int j = 0; j < 4; j++) acc[i][j] = fmaf(xs[i], ws[j], acc[i][j]);
        }
#pragma unroll
        for (int j = 0; j < 4; j++) {
            int o = 4 * oo + j;
            float sc = SC0[o], sh = SH0[o];
            float4 st;
            st.x = fmaxf(fmaf(acc[0][j], sc, sh), 0.0f);
            st.y = fmaxf(fmaf(acc[1][j], sc, sh), 0.0f);
            st.z = fmaxf(fmaf(acc[2][j], sc, sh), 0.0f);
            st.w = fmaxf(fmaf(acc[3][j], sc, sh), 0.0f);
            *(float4*)(HT + o * 36 + 4 * ko) = st;
        }
        __syncthreads();

#pragma unroll
        for (int i = 0; i < 4; i++)
#pragma unroll
            for (int j = 0; j < 4; j++) acc[i][j] = 0.0f;
        for (int c = 0; c < 64; c++) {
            float4 xv = *(const float4*)(HT + c * 36 + 4 * ko);
            float4 wv = *(const float4*)(W1 + c * 64 + 4 * oo);
            float xs[4] = {xv.x, xv.y, xv.z, xv.w};
            float ws[4] = {wv.x, wv.y, wv.z, wv.w};
#pragma unroll
            for (int i = 0; i < 4; i++)
#pragma unroll
                for (int j = 0; j < 4; j++) acc[i][j] = fmaf(xs[i], ws[j], acc[i][j]);
        }
        __syncthreads();
#pragma unroll
        for (int j = 0; j < 4; j++) {
            int o = 4 * oo + j;
            float sc = SC1[o], sh = SH1[o];
            float4 st;
            st.x = fmaxf(fmaf(acc[0][j], sc, sh), 0.0f);
            st.y = fmaxf(fmaf(acc[1][j], sc, sh), 0.0f);
            st.z = fmaxf(fmaf(acc[2][j], sc, sh), 0.0f);
            st.w = fmaxf(fmaf(acc[3][j], sc, sh), 0.0f);
            *(float4*)(HT + o * 36 + 4 * ko) = st;
        }
        __syncthreads();

        float acc2[4][8];
#pragma unroll
        for (int i = 0; i < 4; i++)
#pragma unroll
            for (int j = 0; j < 8; j++) acc2[i][j] = 0.0f;
        for (int c = 0; c < 64; c++) {
            float4 xv = *(const float4*)(HT + c * 36 + 4 * ko);
            float4 wa = *(const float4*)(W2 + c * 128 + 8 * oo);
            float4 wb = *(const float4*)(W2 + c * 128 + 8 * oo + 4);
            float xs[4] = {xv.x, xv.y, xv.z, xv.w};
            float ws[8] = {wa.x, wa.y, wa.z, wa.w, wb.x, wb.y, wb.z, wb.w};
#pragma unroll
            for (int i = 0; i < 4; i++)
#pragma unroll
                for (int j = 0; j < 8; j++) acc2[i][j] = fmaf(xs[i], ws[j], acc2[i][j]);
        }
#pragma unroll
        for (int j = 0; j < 8; j++) {
            int o = 8 * oo + j;
            float sc = SC2[o], sh = SH2[o];
            float mv = 0.0f;
#pragma unroll
            for (int i = 0; i < 4; i++)
                mv = fmaxf(mv, fmaxf(fmaf(acc2[i][j], sc, sh), 0.0f));
            PM[oo * 64 + j * 8 + ko] = mv;
        }
        __syncthreads();

        {
            int o = tid;
            const float* pp = PM + (o >> 3) * 64 + (o & 7) * 8;
            float mv = pp[0];
#pragma unroll
            for (int kk = 1; kk < 8; kk++) mv = fmaxf(mv, pp[kk]);
            outf[((size_t)b * 128 + o) * NPOINT + s] = mv;
        }
        __syncthreads();
    }
}

// =====================================================================
// launcher (sequential; overlap abandoned after 3 failure modes)
// =====================================================================
extern "C" void kernel_launch(void* const* d_in, const int* in_sizes, int n_in,
                              void* d_out, int out_size) {
    const float* xyz  = (const float*)d_in[0];
    const float* feat = (const float*)d_in[1];
    const float* w0 = (const float*)d_in[2];
    const float* g0 = (const float*)d_in[3];
    const float* b0 = (const float*)d_in[4];
    const float* m0 = (const float*)d_in[5];
    const float* v0 = (const float*)d_in[6];
    const float* w1 = (const float*)d_in[7];
    const float* g1 = (const float*)d_in[8];
    const float* b1 = (const float*)d_in[9];
    const float* m1 = (const float*)d_in[10];
    const float* v1 = (const float*)d_in[11];
    const float* w2 = (const float*)d_in[12];
    const float* g2 = (const float*)d_in[13];
    const float* b2 = (const float*)d_in[14];
    const float* m2 = (const float*)d_in[15];
    const float* v2 = (const float*)d_in[16];

    float* out = (float*)d_out;
    float* newxyz  = out;                          // (8,512,3)
    float* newfeat = out + NB * NPOINT * 3;        // (8,128,512)

    cudaFuncSetAttribute(mlp_kernel, cudaFuncAttributeMaxDynamicSharedMemorySize, SM_BYTES);

    fps_kernel<<<NB * 8, 256>>>(xyz, newxyz);
    ballquery_kernel<<<NB * NPOINT / 8, 256>>>(xyz, newxyz);
    mlp_kernel<<<296, 128, SM_BYTES>>>(xyz, feat, newxyz,
                                       w0, g0, b0, m0, v0,
                                       w1, g1, b1, m1, v1,
                                       w2, g2, b2, m2, v2,
                                       newfeat);
}